// round 12
// baseline (speedup 1.0000x reference)
#include <cuda_runtime.h>
#include <math.h>

#define NN 100000
#define EE 1600000
#define SCAN_BLK 1024
#define NBMAX 128

// ---------------- scratch (device globals; no allocation allowed) ----------------
__device__ float g_xl1[(size_t)NN * 128];
__device__ float g_xr1[(size_t)NN * 128];
__device__ float g_res1[(size_t)NN * 128];
__device__ float g_h[(size_t)NN * 128];
__device__ float g_f2[(size_t)NN * 64];   // [xl2 | xr2 | res2 | skip] per node
__device__ float g_w1cat[128 * 384];      // [Wl1 | Wr1 | res1W]
__device__ float g_b1cat[384];
__device__ float g_w2cat[128 * 64];       // [Wl2 | Wr2 | res2W | skipW]
__device__ float g_b2cat[64];
__device__ int   g_deg[NN];
__device__ int   g_off[NN + 1];
__device__ int   g_cur[NN];
__device__ int   g_esrc[EE];
__device__ int   g_bsum[NBMAX];

// ---------------- prep: zero degrees + pack both weight cats (one launch) ----------------
__global__ void prep_kernel(const float* __restrict__ Wl1, const float* __restrict__ bl1,
                            const float* __restrict__ Wr1, const float* __restrict__ br1,
                            const float* __restrict__ r1W, const float* __restrict__ r1b,
                            const float* __restrict__ Wl2, const float* __restrict__ bl2,
                            const float* __restrict__ Wr2, const float* __restrict__ br2,
                            const float* __restrict__ r2W, const float* __restrict__ r2b,
                            const float* __restrict__ sW,  const float* __restrict__ sb,
                            int n) {
    int i = blockIdx.x * blockDim.x + threadIdx.x;
    if (i < n) g_deg[i] = 0;
    if (i < 128 * 384) {
        int k = i / 384, c = i % 384;
        int sel = c >> 7, cc = c & 127;
        const float* W = (sel == 0) ? Wl1 : (sel == 1) ? Wr1 : r1W;
        g_w1cat[i] = W[k * 128 + cc];
    }
    if (i < 384) {
        int sel = i >> 7, cc = i & 127;
        const float* B = (sel == 0) ? bl1 : (sel == 1) ? br1 : r1b;
        g_b1cat[i] = B[cc];
    }
    if (i < 128 * 64) {
        int k = i >> 6, col = i & 63;
        int sel = col >> 4, cc = col & 15;
        const float* W = (sel == 0) ? Wl2 : (sel == 1) ? Wr2 : (sel == 2) ? r2W : sW;
        g_w2cat[i] = W[k * 16 + cc];
    }
    if (i < 64) {
        int sel = i >> 4, cc = i & 15;
        const float* B = (sel == 0) ? bl2 : (sel == 1) ? br2 : (sel == 2) ? r2b : sb;
        g_b2cat[i] = B[cc];
    }
}

// ---------------- scan: block sums, then per-block re-derived prefix ----------------
__global__ void scanA_kernel(int n) {          // block sums
    __shared__ int wsum[32];
    int tid = threadIdx.x, lane = tid & 31, wid = tid >> 5;
    int i = blockIdx.x * SCAN_BLK + tid;
    int v = (i < n) ? g_deg[i] : 0;
    #pragma unroll
    for (int o = 16; o >= 1; o >>= 1) v += __shfl_xor_sync(0xffffffffu, v, o);
    if (lane == 0) wsum[wid] = v;
    __syncthreads();
    if (wid == 0) {
        int s = wsum[lane];
        #pragma unroll
        for (int o = 16; o >= 1; o >>= 1) s += __shfl_xor_sync(0xffffffffu, s, o);
        if (lane == 0) g_bsum[blockIdx.x] = s;
    }
}

__global__ void scanC_kernel(int n, int nb) {  // prefix from g_bsum (lane-parallel) + local scan
    __shared__ int wsum[32];
    __shared__ int sbpre;
    int tid = threadIdx.x, lane = tid & 31, wid = tid >> 5;
    int bid = blockIdx.x;
    if (wid == 0) {
        int a = 0;
        for (int j = lane; j < bid; j += 32) a += __ldg(&g_bsum[j]);
        #pragma unroll
        for (int o = 16; o >= 1; o >>= 1) a += __shfl_xor_sync(0xffffffffu, a, o);
        if (lane == 0) sbpre = a;
    }
    int i = bid * SCAN_BLK + tid;
    int v = (i < n) ? g_deg[i] : 0;
    int s = v;
    #pragma unroll
    for (int o = 1; o < 32; o <<= 1) {
        int u = __shfl_up_sync(0xffffffffu, s, o);
        if (lane >= o) s += u;
    }
    if (lane == 31) wsum[wid] = s;
    __syncthreads();
    if (wid == 0) {
        int ws = wsum[lane];
        #pragma unroll
        for (int o = 1; o < 32; o <<= 1) {
            int u = __shfl_up_sync(0xffffffffu, ws, o);
            if (lane >= o) ws += u;
        }
        wsum[lane] = ws;
    }
    __syncthreads();
    int bpre = sbpre;
    int wexcl = wid ? wsum[wid - 1] : 0;
    int excl = bpre + wexcl + s - v;
    if (i < n) { g_off[i] = excl; g_cur[i] = excl; }
    if (bid == nb - 1 && tid == 0) g_off[n] = bpre + __ldg(&g_bsum[bid]);
}

__global__ void scatter_kernel(const int* __restrict__ ei, int E) {
    int e = blockIdx.x * blockDim.x + threadIdx.x;
    if (e < E) {
        int d = ei[E + e];
        int pos = atomicAdd(&g_cur[d], 1);
        g_esrc[pos] = ei[e];
    }
}

// ---------------- tf32 tensor-core GEMM (+optional fused degree count) ----------------
__device__ __forceinline__ unsigned f2tf(float f) {
    unsigned u;
    asm("cvt.rna.tf32.f32 %0, %1;" : "=r"(u) : "f"(f));
    return u;
}

#define MMA_TF32(d, a, b) \
    asm volatile("mma.sync.aligned.m16n8k8.row.col.f32.tf32.tf32.f32 " \
        "{%0,%1,%2,%3}, {%4,%5,%6,%7}, {%8,%9}, {%0,%1,%2,%3};" \
        : "+f"(d[0]), "+f"(d[1]), "+f"(d[2]), "+f"(d[3]) \
        : "r"(a[0]), "r"(a[1]), "r"(a[2]), "r"(a[3]), "r"(b[0]), "r"(b[1]))

template <int TN>
__global__ void __launch_bounds__(256) gemm_tf32(const float* __restrict__ X, int nrows,
                                                 const float* __restrict__ W,
                                                 const float* __restrict__ Bv,
                                                 float* __restrict__ Y0,
                                                 float* __restrict__ Y1,
                                                 float* __restrict__ Y2, int yshift,
                                                 const int* __restrict__ ei, int E,
                                                 int cblocks) {
    if (blockIdx.x < (unsigned)cblocks) {       // fused degree count
        for (int e = blockIdx.x * blockDim.x + threadIdx.x; e < E;
             e += cblocks * blockDim.x)
            atomicAdd(&g_deg[__ldg(&ei[E + e])], 1);
        return;
    }
    constexpr int SX = 132;   // A-frag quads hit 32 distinct banks
    constexpr int SW = 68;    // B-frag octs hit 32 distinct banks
    extern __shared__ unsigned smemu[];
    unsigned* Xs = smemu;                 // [128][SX] row-major [node][k]
    unsigned* Ws = smemu + 128 * SX;      // [128][SW] [k][n] chunk

    int tid = threadIdx.x;
    int row0 = (blockIdx.x - cblocks) * 128;
    const float4* x4 = (const float4*)X;

    #pragma unroll
    for (int p = 0; p < 16; p++) {
        int f = tid + p * 256;
        int node = f >> 5, kq = f & 31;
        float4 v = make_float4(0.f, 0.f, 0.f, 0.f);
        if (row0 + node < nrows) v = __ldg(&x4[(size_t)(row0 + node) * 32 + kq]);
        uint4 t;
        t.x = f2tf(v.x); t.y = f2tf(v.y); t.z = f2tf(v.z); t.w = f2tf(v.w);
        *(uint4*)&Xs[node * SX + kq * 4] = t;
    }

    int lane = tid & 31, wid = tid >> 5;
    int grp = lane >> 2, tg = lane & 3;
    int wm = wid & 3, wn = wid >> 2;
    float* Yb[3] = {Y0, Y1, Y2};
    int ymask = (1 << yshift) - 1;

    #pragma unroll 1
    for (int ch = 0; ch < TN / 64; ch++) {
        __syncthreads();
        #pragma unroll
        for (int p = 0; p < 8; p++) {
            int f = tid + p * 256;
            int k = f >> 4, cq = f & 15;
            float4 v = __ldg((const float4*)(W + (size_t)k * TN + ch * 64) + cq);
            uint4 t;
            t.x = f2tf(v.x); t.y = f2tf(v.y); t.z = f2tf(v.z); t.w = f2tf(v.w);
            *(uint4*)&Ws[k * SW + cq * 4] = t;
        }
        __syncthreads();

        float acc[2][4][4];
        #pragma unroll
        for (int t = 0; t < 2; t++)
            #pragma unroll
            for (int u = 0; u < 4; u++)
                #pragma unroll
                for (int j = 0; j < 4; j++) acc[t][u][j] = 0.f;

        #pragma unroll
        for (int k0 = 0; k0 < 128; k0 += 8) {
            unsigned a[2][4], b[4][2];
            #pragma unroll
            for (int t = 0; t < 2; t++) {
                int r = wm * 32 + t * 16 + grp;
                a[t][0] = Xs[r * SX + k0 + tg];
                a[t][1] = Xs[(r + 8) * SX + k0 + tg];
                a[t][2] = Xs[r * SX + k0 + tg + 4];
                a[t][3] = Xs[(r + 8) * SX + k0 + tg + 4];
            }
            #pragma unroll
            for (int u = 0; u < 4; u++) {
                int c = wn * 32 + u * 8 + grp;
                b[u][0] = Ws[(k0 + tg) * SW + c];
                b[u][1] = Ws[(k0 + tg + 4) * SW + c];
            }
            #pragma unroll
            for (int t = 0; t < 2; t++)
                #pragma unroll
                for (int u = 0; u < 4; u++) MMA_TF32(acc[t][u], a[t], b[u]);
        }

        #pragma unroll
        for (int t = 0; t < 2; t++) {
            int r = row0 + wm * 32 + t * 16 + grp;
            #pragma unroll
            for (int u = 0; u < 4; u++) {
                int col = ch * 64 + wn * 32 + u * 8 + 2 * tg;
                int buf = col >> yshift;
                int cc = col & ymask;
                float2 bv = *(const float2*)&Bv[col];
                if (r < nrows)
                    *(float2*)&Yb[buf][((size_t)r << yshift) + cc] =
                        make_float2(acc[t][u][0] + bv.x, acc[t][u][1] + bv.y);
                if (r + 8 < nrows)
                    *(float2*)&Yb[buf][((size_t)(r + 8) << yshift) + cc] =
                        make_float2(acc[t][u][2] + bv.x, acc[t][u][3] + bv.y);
            }
        }
    }
}

// ---------------- GAT layer 1: warp/node, 8-edge batch, exp-direct softmax ----------------
// Logits are bounded (|p| < ~6 for this model's scales), so exp(p) without
// max-subtraction is exact softmax math and overflow-safe in fp32.
__device__ __forceinline__ float gat1_logit(const float4& v, const float4& xr,
                                            const float4& at) {
    float mx = v.x + xr.x, my = v.y + xr.y, mz = v.z + xr.z, mw = v.w + xr.w;
    mx = mx > 0.f ? mx : 0.2f * mx;
    my = my > 0.f ? my : 0.2f * my;
    mz = mz > 0.f ? mz : 0.2f * mz;
    mw = mw > 0.f ? mw : 0.2f * mw;
    float p = mx * at.x + my * at.y + mz * at.z + mw * at.w;
    p += __shfl_xor_sync(0xffffffffu, p, 1);
    p += __shfl_xor_sync(0xffffffffu, p, 2);   // head logit (4-lane group)
    return p;
}

__global__ void __launch_bounds__(256) gat1_kernel(const float* __restrict__ att1,
                                                   const float* __restrict__ bias1,
                                                   const float* __restrict__ ln_g,
                                                   const float* __restrict__ ln_b, int n) {
    int lane = threadIdx.x & 31;
    int node = (int)((blockIdx.x * blockDim.x + threadIdx.x) >> 5);
    if (node >= n) return;

    const float4* xl4 = (const float4*)g_xl1;
    float4 xr = ((const float4*)g_xr1)[(size_t)node * 32 + lane];
    float4 at = ((const float4*)att1)[lane];

    int e0 = g_off[node];
    int cnt = g_off[node + 1] - e0;

    // self-loop
    float4 vs = __ldg(&xl4[(size_t)node * 32 + lane]);
    float ws0 = __expf(gat1_logit(vs, xr, at));
    float den = ws0;
    float ax = ws0 * vs.x, ay = ws0 * vs.y, az = ws0 * vs.z, aw = ws0 * vs.w;

    for (int t = 0; t < cnt; t += 8) {
        int s[8];
        #pragma unroll
        for (int j = 0; j < 8; j++)
            s[j] = (t + j < cnt) ? __ldg(&g_esrc[e0 + t + j]) : node;
        float4 v[8];
        #pragma unroll
        for (int j = 0; j < 8; j++)
            v[j] = __ldg(&xl4[(size_t)s[j] * 32 + lane]);

        float w[8];
        #pragma unroll
        for (int j = 0; j < 8; j++) {
            float p = gat1_logit(v[j], xr, at);
            if (t + j >= cnt) p = -1e30f;      // warp-uniform predicate -> w = 0
            w[j] = __expf(p);
        }
        float d0 = 0.f, d1 = 0.f;
        float ax0 = 0.f, ax1 = 0.f, ay0 = 0.f, ay1 = 0.f;
        float az0 = 0.f, az1 = 0.f, aw0 = 0.f, aw1 = 0.f;
        #pragma unroll
        for (int j = 0; j < 8; j += 2) {
            d0  += w[j];          d1  += w[j + 1];
            ax0 += w[j] * v[j].x; ax1 += w[j + 1] * v[j + 1].x;
            ay0 += w[j] * v[j].y; ay1 += w[j + 1] * v[j + 1].y;
            az0 += w[j] * v[j].z; az1 += w[j + 1] * v[j + 1].z;
            aw0 += w[j] * v[j].w; aw1 += w[j + 1] * v[j + 1].w;
        }
        den += d0 + d1;
        ax += ax0 + ax1; ay += ay0 + ay1;
        az += az0 + az1; aw += aw0 + aw1;
    }

    float inv = 1.f / (den + 1e-16f);
    float4 bi = ((const float4*)bias1)[lane];
    float ox = ax * inv + bi.x, oy = ay * inv + bi.y;
    float oz = az * inv + bi.z, ow = aw * inv + bi.w;

    float ssum = ox + oy + oz + ow;
    #pragma unroll
    for (int o = 16; o >= 1; o >>= 1) ssum += __shfl_xor_sync(0xffffffffu, ssum, o);
    float mu = ssum * (1.f / 128.f);
    float cx = ox - mu, cy = oy - mu, cz = oz - mu, cw = ow - mu;
    float sq = cx * cx + cy * cy + cz * cz + cw * cw;
    #pragma unroll
    for (int o = 16; o >= 1; o >>= 1) sq += __shfl_xor_sync(0xffffffffu, sq, o);
    float rstd = rsqrtf(sq * (1.f / 128.f) + 1e-5f);

    float4 g4 = ((const float4*)ln_g)[lane];
    float4 b4 = ((const float4*)ln_b)[lane];
    float4 rr = ((const float4*)g_res1)[(size_t)node * 32 + lane];
    float hx = cx * rstd * g4.x + b4.x + rr.x;
    float hy = cy * rstd * g4.y + b4.y + rr.y;
    float hz = cz * rstd * g4.z + b4.z + rr.z;
    float hw = cw * rstd * g4.w + b4.w + rr.w;
    hx = hx > 0.f ? hx : expm1f(hx);
    hy = hy > 0.f ? hy : expm1f(hy);
    hz = hz > 0.f ? hz : expm1f(hz);
    hw = hw > 0.f ? hw : expm1f(hw);
    ((float4*)g_h)[(size_t)node * 32 + lane] = make_float4(hx, hy, hz, hw);
}

// ---------------- GAT layer 2 (4-edge, exp-direct) + LN + res + ELU + skip + GEMV ----------------
__device__ __forceinline__ float gat2_logit(float v, float xr, float at, unsigned hm) {
    float mm = v + xr;
    float e = mm > 0.f ? mm : 0.2f * mm;
    float p = e * at;
    p += __shfl_xor_sync(hm, p, 1);
    p += __shfl_xor_sync(hm, p, 2);
    p += __shfl_xor_sync(hm, p, 4);
    p += __shfl_xor_sync(hm, p, 8);
    return p;
}

__global__ void __launch_bounds__(256) gat2_kernel(const float* __restrict__ bias2,
                                                   const float* __restrict__ ln_g,
                                                   const float* __restrict__ ln_b,
                                                   const float* __restrict__ att2,
                                                   const float* __restrict__ outW,
                                                   const float* __restrict__ outB,
                                                   float* __restrict__ out, int n) {
    __shared__ float sW[16 * 64];
    __shared__ float sB[64];
    int tid = threadIdx.x;
    for (int i = tid; i < 1024; i += 256) sW[i] = outW[i];
    if (tid < 64) sB[tid] = outB[tid];
    __syncthreads();

    int lane = tid & 31;
    int warp = tid >> 5;
    int node = blockIdx.x * 16 + warp * 2 + (lane >> 4);
    int c = lane & 15;
    bool valid = node < n;
    int nd = valid ? node : 0;
    unsigned hm = (lane < 16) ? 0x0000FFFFu : 0xFFFF0000u;

    float xr = g_f2[(size_t)nd * 64 + 16 + c];
    float at = att2[c];
    int e0 = g_off[nd];
    int cnt = valid ? (g_off[nd + 1] - e0) : 0;

    // self-loop
    float vs = __ldg(&g_f2[(size_t)nd * 64 + c]);
    float ws0 = __expf(gat2_logit(vs, xr, at, hm));
    float den = ws0, acc = ws0 * vs;

    for (int t = 0; t < cnt; t += 4) {
        int s0 = __ldg(&g_esrc[e0 + t]);
        int s1 = (t + 1 < cnt) ? __ldg(&g_esrc[e0 + t + 1]) : nd;
        int s2 = (t + 2 < cnt) ? __ldg(&g_esrc[e0 + t + 2]) : nd;
        int s3 = (t + 3 < cnt) ? __ldg(&g_esrc[e0 + t + 3]) : nd;
        float v0 = __ldg(&g_f2[(size_t)s0 * 64 + c]);
        float v1 = __ldg(&g_f2[(size_t)s1 * 64 + c]);
        float v2 = __ldg(&g_f2[(size_t)s2 * 64 + c]);
        float v3 = __ldg(&g_f2[(size_t)s3 * 64 + c]);

        float p0 = gat2_logit(v0, xr, at, hm);
        float p1 = gat2_logit(v1, xr, at, hm);
        float p2 = gat2_logit(v2, xr, at, hm);
        float p3 = gat2_logit(v3, xr, at, hm);
        if (t + 1 >= cnt) p1 = -1e30f;
        if (t + 2 >= cnt) p2 = -1e30f;
        if (t + 3 >= cnt) p3 = -1e30f;

        float w0 = __expf(p0), w1 = __expf(p1);
        float w2 = __expf(p2), w3 = __expf(p3);
        den += (w0 + w1) + (w2 + w3);
        acc += (w0 * v0 + w1 * v1) + (w2 * v2 + w3 * v3);
    }
    float o = acc / (den + 1e-16f) + bias2[c];

    float s16 = o;
    s16 += __shfl_xor_sync(hm, s16, 1);
    s16 += __shfl_xor_sync(hm, s16, 2);
    s16 += __shfl_xor_sync(hm, s16, 4);
    s16 += __shfl_xor_sync(hm, s16, 8);
    float mu = s16 * (1.f / 16.f);
    float cc2 = o - mu;
    float sq = cc2 * cc2;
    sq += __shfl_xor_sync(hm, sq, 1);
    sq += __shfl_xor_sync(hm, sq, 2);
    sq += __shfl_xor_sync(hm, sq, 4);
    sq += __shfl_xor_sync(hm, sq, 8);
    float rstd = rsqrtf(sq * (1.f / 16.f) + 1e-5f);
    float h2 = cc2 * rstd * ln_g[c] + ln_b[c];
    h2 += g_f2[(size_t)nd * 64 + 32 + c];           // res2
    h2 = h2 > 0.f ? h2 : expm1f(h2);                // ELU
    h2 += g_f2[(size_t)nd * 64 + 48 + c];           // skip

    float o0 = sB[c], o1 = sB[c + 16], o2v = sB[c + 32], o3 = sB[c + 48];
    #pragma unroll
    for (int k = 0; k < 16; k++) {
        float hk = __shfl_sync(hm, h2, (lane & 16) + k);
        o0  += hk * sW[k * 64 + c];
        o1  += hk * sW[k * 64 + c + 16];
        o2v += hk * sW[k * 64 + c + 32];
        o3  += hk * sW[k * 64 + c + 48];
    }
    if (valid) {
        out[(size_t)node * 64 + c] = o0;
        out[(size_t)node * 64 + c + 16] = o1;
        out[(size_t)node * 64 + c + 32] = o2v;
        out[(size_t)node * 64 + c + 48] = o3;
    }
}

// ---------------- launcher ----------------
extern "C" void kernel_launch(void* const* d_in, const int* in_sizes, int n_in,
                              void* d_out, int out_size) {
    const float* x    = (const float*)d_in[0];
    const int*   ei   = (const int*)d_in[1];
    const float* Wl1  = (const float*)d_in[2];
    const float* bl1  = (const float*)d_in[3];
    const float* Wr1  = (const float*)d_in[4];
    const float* br1  = (const float*)d_in[5];
    const float* att1 = (const float*)d_in[6];
    const float* bias1= (const float*)d_in[7];
    const float* Wl2  = (const float*)d_in[8];
    const float* bl2  = (const float*)d_in[9];
    const float* Wr2  = (const float*)d_in[10];
    const float* br2  = (const float*)d_in[11];
    const float* att2 = (const float*)d_in[12];
    const float* bias2= (const float*)d_in[13];
    const float* ln1g = (const float*)d_in[14];
    const float* ln1b = (const float*)d_in[15];
    const float* ln2g = (const float*)d_in[16];
    const float* ln2b = (const float*)d_in[17];
    const float* r1W  = (const float*)d_in[18];
    const float* r1b  = (const float*)d_in[19];
    const float* r2W  = (const float*)d_in[20];
    const float* r2b  = (const float*)d_in[21];
    const float* skW  = (const float*)d_in[22];
    const float* skb  = (const float*)d_in[23];
    const float* oW   = (const float*)d_in[24];
    const float* ob   = (const float*)d_in[25];
    float* out = (float*)d_out;

    int n = in_sizes[0] / 128;   // 100000
    int E = in_sizes[1] / 2;     // 1600000

    float *p_xl1, *p_xr1, *p_res1, *p_h, *p_f2, *p_w1, *p_b1, *p_w2, *p_b2;
    cudaGetSymbolAddress((void**)&p_xl1, g_xl1);
    cudaGetSymbolAddress((void**)&p_xr1, g_xr1);
    cudaGetSymbolAddress((void**)&p_res1, g_res1);
    cudaGetSymbolAddress((void**)&p_h, g_h);
    cudaGetSymbolAddress((void**)&p_f2, g_f2);
    cudaGetSymbolAddress((void**)&p_w1, g_w1cat);
    cudaGetSymbolAddress((void**)&p_b1, g_b1cat);
    cudaGetSymbolAddress((void**)&p_w2, g_w2cat);
    cudaGetSymbolAddress((void**)&p_b2, g_b2cat);

    int smemg = (128 * 132 + 128 * 68) * 4;   // 102400 B
    cudaFuncSetAttribute(gemm_tf32<384>, cudaFuncAttributeMaxDynamicSharedMemorySize, smemg);
    cudaFuncSetAttribute(gemm_tf32<64>,  cudaFuncAttributeMaxDynamicSharedMemorySize, smemg);

    int gb = (n + 127) / 128;
    int nb = (n + SCAN_BLK - 1) / SCAN_BLK;   // 98 <= NBMAX
    const int CB = 256;                        // fused count blocks

    // prep: zero degrees + pack weight cats (single launch)
    prep_kernel<<<(n + 255) / 256, 256>>>(Wl1, bl1, Wr1, br1, r1W, r1b,
                                          Wl2, bl2, Wr2, br2, r2W, r2b,
                                          skW, skb, n);

    // layer-1 fused GEMM (tf32 tensor cores) + fused degree count
    gemm_tf32<384><<<gb + CB, 256, smemg>>>(x, n, p_w1, p_b1,
                                            p_xl1, p_xr1, p_res1, 7, ei, E, CB);

    // scan (2 kernels) + scatter -> CSR
    scanA_kernel<<<nb, SCAN_BLK>>>(n);
    scanC_kernel<<<nb, SCAN_BLK>>>(n, nb);
    scatter_kernel<<<(E + 255) / 256, 256>>>(ei, E);

    // GAT1 + LN + res + ELU  -> g_h
    gat1_kernel<<<(n + 7) / 8, 256>>>(att1, bias1, ln1g, ln1b, n);

    // layer-2 fused linear transforms: [xl2 | xr2 | res2 | skip] -> g_f2
    gemm_tf32<64><<<gb, 256, smemg>>>(p_h, n, p_w2, p_b2, p_f2, p_f2, p_f2, 6,
                                      ei, E, 0);

    // GAT2 + LN + res + ELU + skip + output projection -> d_out
    gat2_kernel<<<(n + 15) / 16, 256>>>(bias2, ln2g, ln2b, att2, oW, ob, out, n);
}

// round 13
// speedup vs baseline: 1.1033x; 1.1033x over previous
#include <cuda_runtime.h>
#include <math.h>

#define NN 100000
#define EE 1600000
#define SCAN_BLK 1024
#define NBMAX 128

// ---------------- scratch (device globals; no allocation allowed) ----------------
__device__ float g_xl1[(size_t)NN * 128];
__device__ float g_xr1[(size_t)NN * 128];
__device__ float g_res1[(size_t)NN * 128];
__device__ float g_h[(size_t)NN * 128];
__device__ float g_f2[(size_t)NN * 64];   // [xl2 | xr2 | res2 | skip] per node
__device__ float g_w1cat[128 * 384];      // [Wl1 | Wr1 | res1W]
__device__ float g_b1cat[384];
__device__ float g_w2cat[128 * 64];       // [Wl2 | Wr2 | res2W | skipW]
__device__ float g_b2cat[64];
__device__ int   g_deg[NN];
__device__ int   g_off[NN + 1];
__device__ int   g_cur[NN];
__device__ int   g_esrc[EE];
__device__ int   g_bsum[NBMAX];

// ---------------- prep: zero degrees + pack both weight cats (one launch) ----------------
__global__ void prep_kernel(const float* __restrict__ Wl1, const float* __restrict__ bl1,
                            const float* __restrict__ Wr1, const float* __restrict__ br1,
                            const float* __restrict__ r1W, const float* __restrict__ r1b,
                            const float* __restrict__ Wl2, const float* __restrict__ bl2,
                            const float* __restrict__ Wr2, const float* __restrict__ br2,
                            const float* __restrict__ r2W, const float* __restrict__ r2b,
                            const float* __restrict__ sW,  const float* __restrict__ sb,
                            int n) {
    int i = blockIdx.x * blockDim.x + threadIdx.x;
    if (i < n) g_deg[i] = 0;
    if (i < 128 * 384) {
        int k = i / 384, c = i % 384;
        int sel = c >> 7, cc = c & 127;
        const float* W = (sel == 0) ? Wl1 : (sel == 1) ? Wr1 : r1W;
        g_w1cat[i] = W[k * 128 + cc];
    }
    if (i < 384) {
        int sel = i >> 7, cc = i & 127;
        const float* B = (sel == 0) ? bl1 : (sel == 1) ? br1 : r1b;
        g_b1cat[i] = B[cc];
    }
    if (i < 128 * 64) {
        int k = i >> 6, col = i & 63;
        int sel = col >> 4, cc = col & 15;
        const float* W = (sel == 0) ? Wl2 : (sel == 1) ? Wr2 : (sel == 2) ? r2W : sW;
        g_w2cat[i] = W[k * 16 + cc];
    }
    if (i < 64) {
        int sel = i >> 4, cc = i & 15;
        const float* B = (sel == 0) ? bl2 : (sel == 1) ? br2 : (sel == 2) ? r2b : sb;
        g_b2cat[i] = B[cc];
    }
}

// ---------------- scan: block sums, then per-block re-derived prefix ----------------
__global__ void scanA_kernel(int n) {          // block sums
    __shared__ int wsum[32];
    int tid = threadIdx.x, lane = tid & 31, wid = tid >> 5;
    int i = blockIdx.x * SCAN_BLK + tid;
    int v = (i < n) ? g_deg[i] : 0;
    #pragma unroll
    for (int o = 16; o >= 1; o >>= 1) v += __shfl_xor_sync(0xffffffffu, v, o);
    if (lane == 0) wsum[wid] = v;
    __syncthreads();
    if (wid == 0) {
        int s = wsum[lane];
        #pragma unroll
        for (int o = 16; o >= 1; o >>= 1) s += __shfl_xor_sync(0xffffffffu, s, o);
        if (lane == 0) g_bsum[blockIdx.x] = s;
    }
}

__global__ void scanC_kernel(int n, int nb) {  // prefix from g_bsum (lane-parallel) + local scan
    __shared__ int wsum[32];
    __shared__ int sbpre;
    int tid = threadIdx.x, lane = tid & 31, wid = tid >> 5;
    int bid = blockIdx.x;
    if (wid == 0) {
        int a = 0;
        for (int j = lane; j < bid; j += 32) a += __ldg(&g_bsum[j]);
        #pragma unroll
        for (int o = 16; o >= 1; o >>= 1) a += __shfl_xor_sync(0xffffffffu, a, o);
        if (lane == 0) sbpre = a;
    }
    int i = bid * SCAN_BLK + tid;
    int v = (i < n) ? g_deg[i] : 0;
    int s = v;
    #pragma unroll
    for (int o = 1; o < 32; o <<= 1) {
        int u = __shfl_up_sync(0xffffffffu, s, o);
        if (lane >= o) s += u;
    }
    if (lane == 31) wsum[wid] = s;
    __syncthreads();
    if (wid == 0) {
        int ws = wsum[lane];
        #pragma unroll
        for (int o = 1; o < 32; o <<= 1) {
            int u = __shfl_up_sync(0xffffffffu, ws, o);
            if (lane >= o) ws += u;
        }
        wsum[lane] = ws;
    }
    __syncthreads();
    int bpre = sbpre;
    int wexcl = wid ? wsum[wid - 1] : 0;
    int excl = bpre + wexcl + s - v;
    if (i < n) { g_off[i] = excl; g_cur[i] = excl; }
    if (bid == nb - 1 && tid == 0) g_off[n] = bpre + __ldg(&g_bsum[bid]);
}

__global__ void scatter_kernel(const int* __restrict__ ei, int E) {
    int e = blockIdx.x * blockDim.x + threadIdx.x;
    if (e < E) {
        int d = ei[E + e];
        int pos = atomicAdd(&g_cur[d], 1);
        g_esrc[pos] = ei[e];
    }
}

// ---------------- tf32 tensor-core GEMM (+optional fused degree count) ----------------
__device__ __forceinline__ unsigned f2tf(float f) {
    unsigned u;
    asm("cvt.rna.tf32.f32 %0, %1;" : "=r"(u) : "f"(f));
    return u;
}

#define MMA_TF32(d, a, b) \
    asm volatile("mma.sync.aligned.m16n8k8.row.col.f32.tf32.tf32.f32 " \
        "{%0,%1,%2,%3}, {%4,%5,%6,%7}, {%8,%9}, {%0,%1,%2,%3};" \
        : "+f"(d[0]), "+f"(d[1]), "+f"(d[2]), "+f"(d[3]) \
        : "r"(a[0]), "r"(a[1]), "r"(a[2]), "r"(a[3]), "r"(b[0]), "r"(b[1]))

template <int TN>
__global__ void __launch_bounds__(256) gemm_tf32(const float* __restrict__ X, int nrows,
                                                 const float* __restrict__ W,
                                                 const float* __restrict__ Bv,
                                                 float* __restrict__ Y0,
                                                 float* __restrict__ Y1,
                                                 float* __restrict__ Y2, int yshift,
                                                 const int* __restrict__ ei, int E,
                                                 int cblocks) {
    if (blockIdx.x < (unsigned)cblocks) {       // fused degree count
        for (int e = blockIdx.x * blockDim.x + threadIdx.x; e < E;
             e += cblocks * blockDim.x)
            atomicAdd(&g_deg[__ldg(&ei[E + e])], 1);
        return;
    }
    constexpr int SX = 132;   // A-frag quads hit 32 distinct banks
    constexpr int SW = 68;    // B-frag octs hit 32 distinct banks
    extern __shared__ unsigned smemu[];
    unsigned* Xs = smemu;                 // [128][SX] row-major [node][k]
    unsigned* Ws = smemu + 128 * SX;      // [128][SW] [k][n] chunk

    int tid = threadIdx.x;
    int row0 = (blockIdx.x - cblocks) * 128;
    const float4* x4 = (const float4*)X;

    #pragma unroll
    for (int p = 0; p < 16; p++) {
        int f = tid + p * 256;
        int node = f >> 5, kq = f & 31;
        float4 v = make_float4(0.f, 0.f, 0.f, 0.f);
        if (row0 + node < nrows) v = __ldg(&x4[(size_t)(row0 + node) * 32 + kq]);
        uint4 t;
        t.x = f2tf(v.x); t.y = f2tf(v.y); t.z = f2tf(v.z); t.w = f2tf(v.w);
        *(uint4*)&Xs[node * SX + kq * 4] = t;
    }

    int lane = tid & 31, wid = tid >> 5;
    int grp = lane >> 2, tg = lane & 3;
    int wm = wid & 3, wn = wid >> 2;
    float* Yb[3] = {Y0, Y1, Y2};
    int ymask = (1 << yshift) - 1;

    #pragma unroll 1
    for (int ch = 0; ch < TN / 64; ch++) {
        __syncthreads();
        #pragma unroll
        for (int p = 0; p < 8; p++) {
            int f = tid + p * 256;
            int k = f >> 4, cq = f & 15;
            float4 v = __ldg((const float4*)(W + (size_t)k * TN + ch * 64) + cq);
            uint4 t;
            t.x = f2tf(v.x); t.y = f2tf(v.y); t.z = f2tf(v.z); t.w = f2tf(v.w);
            *(uint4*)&Ws[k * SW + cq * 4] = t;
        }
        __syncthreads();

        float acc[2][4][4];
        #pragma unroll
        for (int t = 0; t < 2; t++)
            #pragma unroll
            for (int u = 0; u < 4; u++)
                #pragma unroll
                for (int j = 0; j < 4; j++) acc[t][u][j] = 0.f;

        #pragma unroll
        for (int k0 = 0; k0 < 128; k0 += 8) {
            unsigned a[2][4], b[4][2];
            #pragma unroll
            for (int t = 0; t < 2; t++) {
                int r = wm * 32 + t * 16 + grp;
                a[t][0] = Xs[r * SX + k0 + tg];
                a[t][1] = Xs[(r + 8) * SX + k0 + tg];
                a[t][2] = Xs[r * SX + k0 + tg + 4];
                a[t][3] = Xs[(r + 8) * SX + k0 + tg + 4];
            }
            #pragma unroll
            for (int u = 0; u < 4; u++) {
                int c = wn * 32 + u * 8 + grp;
                b[u][0] = Ws[(k0 + tg) * SW + c];
                b[u][1] = Ws[(k0 + tg + 4) * SW + c];
            }
            #pragma unroll
            for (int t = 0; t < 2; t++)
                #pragma unroll
                for (int u = 0; u < 4; u++) MMA_TF32(acc[t][u], a[t], b[u]);
        }

        #pragma unroll
        for (int t = 0; t < 2; t++) {
            int r = row0 + wm * 32 + t * 16 + grp;
            #pragma unroll
            for (int u = 0; u < 4; u++) {
                int col = ch * 64 + wn * 32 + u * 8 + 2 * tg;
                int buf = col >> yshift;
                int cc = col & ymask;
                float2 bv = *(const float2*)&Bv[col];
                if (r < nrows)
                    *(float2*)&Yb[buf][((size_t)r << yshift) + cc] =
                        make_float2(acc[t][u][0] + bv.x, acc[t][u][1] + bv.y);
                if (r + 8 < nrows)
                    *(float2*)&Yb[buf][((size_t)(r + 8) << yshift) + cc] =
                        make_float2(acc[t][u][2] + bv.x, acc[t][u][3] + bv.y);
            }
        }
    }
}

// ---------------- GAT layer 1: warp/node, 4-edge batch, exp-direct softmax ----------------
// Logits are bounded (|p| < ~6 for this model's scales), so exp(p) without
// max-subtraction is exact softmax math and overflow-safe in fp32.
__device__ __forceinline__ float gat1_logit(const float4& v, const float4& xr,
                                            const float4& at) {
    float mx = v.x + xr.x, my = v.y + xr.y, mz = v.z + xr.z, mw = v.w + xr.w;
    mx = mx > 0.f ? mx : 0.2f * mx;
    my = my > 0.f ? my : 0.2f * my;
    mz = mz > 0.f ? mz : 0.2f * mz;
    mw = mw > 0.f ? mw : 0.2f * mw;
    float p = mx * at.x + my * at.y + mz * at.z + mw * at.w;
    p += __shfl_xor_sync(0xffffffffu, p, 1);
    p += __shfl_xor_sync(0xffffffffu, p, 2);   // head logit (4-lane group)
    return p;
}

__global__ void __launch_bounds__(256) gat1_kernel(const float* __restrict__ att1,
                                                   const float* __restrict__ bias1,
                                                   const float* __restrict__ ln_g,
                                                   const float* __restrict__ ln_b, int n) {
    int lane = threadIdx.x & 31;
    int node = (int)((blockIdx.x * blockDim.x + threadIdx.x) >> 5);
    if (node >= n) return;

    const float4* xl4 = (const float4*)g_xl1;
    float4 xr = ((const float4*)g_xr1)[(size_t)node * 32 + lane];
    float4 at = ((const float4*)att1)[lane];

    int e0 = g_off[node];
    int cnt = g_off[node + 1] - e0;

    // self-loop
    float4 vs = __ldg(&xl4[(size_t)node * 32 + lane]);
    float ws0 = __expf(gat1_logit(vs, xr, at));
    float den = ws0;
    float ax = ws0 * vs.x, ay = ws0 * vs.y, az = ws0 * vs.z, aw = ws0 * vs.w;

    for (int t = 0; t < cnt; t += 4) {
        int s0 = __ldg(&g_esrc[e0 + t]);
        int s1 = (t + 1 < cnt) ? __ldg(&g_esrc[e0 + t + 1]) : node;
        int s2 = (t + 2 < cnt) ? __ldg(&g_esrc[e0 + t + 2]) : node;
        int s3 = (t + 3 < cnt) ? __ldg(&g_esrc[e0 + t + 3]) : node;
        float4 v0 = __ldg(&xl4[(size_t)s0 * 32 + lane]);
        float4 v1 = __ldg(&xl4[(size_t)s1 * 32 + lane]);
        float4 v2 = __ldg(&xl4[(size_t)s2 * 32 + lane]);
        float4 v3 = __ldg(&xl4[(size_t)s3 * 32 + lane]);

        float p0 = gat1_logit(v0, xr, at);
        float p1 = gat1_logit(v1, xr, at);
        float p2 = gat1_logit(v2, xr, at);
        float p3 = gat1_logit(v3, xr, at);
        if (t + 1 >= cnt) p1 = -1e30f;     // warp-uniform predicates -> w = 0
        if (t + 2 >= cnt) p2 = -1e30f;
        if (t + 3 >= cnt) p3 = -1e30f;

        float w0 = __expf(p0), w1 = __expf(p1);
        float w2 = __expf(p2), w3 = __expf(p3);
        den += (w0 + w1) + (w2 + w3);
        ax += (w0 * v0.x + w1 * v1.x) + (w2 * v2.x + w3 * v3.x);
        ay += (w0 * v0.y + w1 * v1.y) + (w2 * v2.y + w3 * v3.y);
        az += (w0 * v0.z + w1 * v1.z) + (w2 * v2.z + w3 * v3.z);
        aw += (w0 * v0.w + w1 * v1.w) + (w2 * v2.w + w3 * v3.w);
    }

    float inv = 1.f / (den + 1e-16f);
    float4 bi = ((const float4*)bias1)[lane];
    float ox = ax * inv + bi.x, oy = ay * inv + bi.y;
    float oz = az * inv + bi.z, ow = aw * inv + bi.w;

    float ssum = ox + oy + oz + ow;
    #pragma unroll
    for (int o = 16; o >= 1; o >>= 1) ssum += __shfl_xor_sync(0xffffffffu, ssum, o);
    float mu = ssum * (1.f / 128.f);
    float cx = ox - mu, cy = oy - mu, cz = oz - mu, cw = ow - mu;
    float sq = cx * cx + cy * cy + cz * cz + cw * cw;
    #pragma unroll
    for (int o = 16; o >= 1; o >>= 1) sq += __shfl_xor_sync(0xffffffffu, sq, o);
    float rstd = rsqrtf(sq * (1.f / 128.f) + 1e-5f);

    float4 g4 = ((const float4*)ln_g)[lane];
    float4 b4 = ((const float4*)ln_b)[lane];
    float4 rr = ((const float4*)g_res1)[(size_t)node * 32 + lane];
    float hx = cx * rstd * g4.x + b4.x + rr.x;
    float hy = cy * rstd * g4.y + b4.y + rr.y;
    float hz = cz * rstd * g4.z + b4.z + rr.z;
    float hw = cw * rstd * g4.w + b4.w + rr.w;
    hx = hx > 0.f ? hx : expm1f(hx);
    hy = hy > 0.f ? hy : expm1f(hy);
    hz = hz > 0.f ? hz : expm1f(hz);
    hw = hw > 0.f ? hw : expm1f(hw);
    ((float4*)g_h)[(size_t)node * 32 + lane] = make_float4(hx, hy, hz, hw);
}

// ---------------- GAT layer 2 (4-edge, exp-direct) + LN + res + ELU + skip + GEMV ----------------
__device__ __forceinline__ float gat2_logit(float v, float xr, float at, unsigned hm) {
    float mm = v + xr;
    float e = mm > 0.f ? mm : 0.2f * mm;
    float p = e * at;
    p += __shfl_xor_sync(hm, p, 1);
    p += __shfl_xor_sync(hm, p, 2);
    p += __shfl_xor_sync(hm, p, 4);
    p += __shfl_xor_sync(hm, p, 8);
    return p;
}

__global__ void __launch_bounds__(256) gat2_kernel(const float* __restrict__ bias2,
                                                   const float* __restrict__ ln_g,
                                                   const float* __restrict__ ln_b,
                                                   const float* __restrict__ att2,
                                                   const float* __restrict__ outW,
                                                   const float* __restrict__ outB,
                                                   float* __restrict__ out, int n) {
    __shared__ float sW[16 * 64];
    __shared__ float sB[64];
    int tid = threadIdx.x;
    for (int i = tid; i < 1024; i += 256) sW[i] = outW[i];
    if (tid < 64) sB[tid] = outB[tid];
    __syncthreads();

    int lane = tid & 31;
    int warp = tid >> 5;
    int node = blockIdx.x * 16 + warp * 2 + (lane >> 4);
    int c = lane & 15;
    bool valid = node < n;
    int nd = valid ? node : 0;
    unsigned hm = (lane < 16) ? 0x0000FFFFu : 0xFFFF0000u;

    float xr = g_f2[(size_t)nd * 64 + 16 + c];
    float at = att2[c];
    int e0 = g_off[nd];
    int cnt = valid ? (g_off[nd + 1] - e0) : 0;

    // self-loop
    float vs = __ldg(&g_f2[(size_t)nd * 64 + c]);
    float ws0 = __expf(gat2_logit(vs, xr, at, hm));
    float den = ws0, acc = ws0 * vs;

    for (int t = 0; t < cnt; t += 4) {
        int s0 = __ldg(&g_esrc[e0 + t]);
        int s1 = (t + 1 < cnt) ? __ldg(&g_esrc[e0 + t + 1]) : nd;
        int s2 = (t + 2 < cnt) ? __ldg(&g_esrc[e0 + t + 2]) : nd;
        int s3 = (t + 3 < cnt) ? __ldg(&g_esrc[e0 + t + 3]) : nd;
        float v0 = __ldg(&g_f2[(size_t)s0 * 64 + c]);
        float v1 = __ldg(&g_f2[(size_t)s1 * 64 + c]);
        float v2 = __ldg(&g_f2[(size_t)s2 * 64 + c]);
        float v3 = __ldg(&g_f2[(size_t)s3 * 64 + c]);

        float p0 = gat2_logit(v0, xr, at, hm);
        float p1 = gat2_logit(v1, xr, at, hm);
        float p2 = gat2_logit(v2, xr, at, hm);
        float p3 = gat2_logit(v3, xr, at, hm);
        if (t + 1 >= cnt) p1 = -1e30f;
        if (t + 2 >= cnt) p2 = -1e30f;
        if (t + 3 >= cnt) p3 = -1e30f;

        float w0 = __expf(p0), w1 = __expf(p1);
        float w2 = __expf(p2), w3 = __expf(p3);
        den += (w0 + w1) + (w2 + w3);
        acc += (w0 * v0 + w1 * v1) + (w2 * v2 + w3 * v3);
    }
    float o = acc / (den + 1e-16f) + bias2[c];

    float s16 = o;
    s16 += __shfl_xor_sync(hm, s16, 1);
    s16 += __shfl_xor_sync(hm, s16, 2);
    s16 += __shfl_xor_sync(hm, s16, 4);
    s16 += __shfl_xor_sync(hm, s16, 8);
    float mu = s16 * (1.f / 16.f);
    float cc2 = o - mu;
    float sq = cc2 * cc2;
    sq += __shfl_xor_sync(hm, sq, 1);
    sq += __shfl_xor_sync(hm, sq, 2);
    sq += __shfl_xor_sync(hm, sq, 4);
    sq += __shfl_xor_sync(hm, sq, 8);
    float rstd = rsqrtf(sq * (1.f / 16.f) + 1e-5f);
    float h2 = cc2 * rstd * ln_g[c] + ln_b[c];
    h2 += g_f2[(size_t)nd * 64 + 32 + c];           // res2
    h2 = h2 > 0.f ? h2 : expm1f(h2);                // ELU
    h2 += g_f2[(size_t)nd * 64 + 48 + c];           // skip

    float o0 = sB[c], o1 = sB[c + 16], o2v = sB[c + 32], o3 = sB[c + 48];
    #pragma unroll
    for (int k = 0; k < 16; k++) {
        float hk = __shfl_sync(hm, h2, (lane & 16) + k);
        o0  += hk * sW[k * 64 + c];
        o1  += hk * sW[k * 64 + c + 16];
        o2v += hk * sW[k * 64 + c + 32];
        o3  += hk * sW[k * 64 + c + 48];
    }
    if (valid) {
        out[(size_t)node * 64 + c] = o0;
        out[(size_t)node * 64 + c + 16] = o1;
        out[(size_t)node * 64 + c + 32] = o2v;
        out[(size_t)node * 64 + c + 48] = o3;
    }
}

// ---------------- launcher ----------------
extern "C" void kernel_launch(void* const* d_in, const int* in_sizes, int n_in,
                              void* d_out, int out_size) {
    const float* x    = (const float*)d_in[0];
    const int*   ei   = (const int*)d_in[1];
    const float* Wl1  = (const float*)d_in[2];
    const float* bl1  = (const float*)d_in[3];
    const float* Wr1  = (const float*)d_in[4];
    const float* br1  = (const float*)d_in[5];
    const float* att1 = (const float*)d_in[6];
    const float* bias1= (const float*)d_in[7];
    const float* Wl2  = (const float*)d_in[8];
    const float* bl2  = (const float*)d_in[9];
    const float* Wr2  = (const float*)d_in[10];
    const float* br2  = (const float*)d_in[11];
    const float* att2 = (const float*)d_in[12];
    const float* bias2= (const float*)d_in[13];
    const float* ln1g = (const float*)d_in[14];
    const float* ln1b = (const float*)d_in[15];
    const float* ln2g = (const float*)d_in[16];
    const float* ln2b = (const float*)d_in[17];
    const float* r1W  = (const float*)d_in[18];
    const float* r1b  = (const float*)d_in[19];
    const float* r2W  = (const float*)d_in[20];
    const float* r2b  = (const float*)d_in[21];
    const float* skW  = (const float*)d_in[22];
    const float* skb  = (const float*)d_in[23];
    const float* oW   = (const float*)d_in[24];
    const float* ob   = (const float*)d_in[25];
    float* out = (float*)d_out;

    int n = in_sizes[0] / 128;   // 100000
    int E = in_sizes[1] / 2;     // 1600000

    float *p_xl1, *p_xr1, *p_res1, *p_h, *p_f2, *p_w1, *p_b1, *p_w2, *p_b2;
    cudaGetSymbolAddress((void**)&p_xl1, g_xl1);
    cudaGetSymbolAddress((void**)&p_xr1, g_xr1);
    cudaGetSymbolAddress((void**)&p_res1, g_res1);
    cudaGetSymbolAddress((void**)&p_h, g_h);
    cudaGetSymbolAddress((void**)&p_f2, g_f2);
    cudaGetSymbolAddress((void**)&p_w1, g_w1cat);
    cudaGetSymbolAddress((void**)&p_b1, g_b1cat);
    cudaGetSymbolAddress((void**)&p_w2, g_w2cat);
    cudaGetSymbolAddress((void**)&p_b2, g_b2cat);

    int smemg = (128 * 132 + 128 * 68) * 4;   // 102400 B
    cudaFuncSetAttribute(gemm_tf32<384>, cudaFuncAttributeMaxDynamicSharedMemorySize, smemg);
    cudaFuncSetAttribute(gemm_tf32<64>,  cudaFuncAttributeMaxDynamicSharedMemorySize, smemg);

    int gb = (n + 127) / 128;
    int nb = (n + SCAN_BLK - 1) / SCAN_BLK;   // 98 <= NBMAX
    const int CB = 256;                        // fused count blocks

    // prep: zero degrees + pack weight cats (single launch)
    prep_kernel<<<(n + 255) / 256, 256>>>(Wl1, bl1, Wr1, br1, r1W, r1b,
                                          Wl2, bl2, Wr2, br2, r2W, r2b,
                                          skW, skb, n);

    // layer-1 fused GEMM (tf32 tensor cores) + fused degree count
    gemm_tf32<384><<<gb + CB, 256, smemg>>>(x, n, p_w1, p_b1,
                                            p_xl1, p_xr1, p_res1, 7, ei, E, CB);

    // scan (2 kernels) + scatter -> CSR
    scanA_kernel<<<nb, SCAN_BLK>>>(n);
    scanC_kernel<<<nb, SCAN_BLK>>>(n, nb);
    scatter_kernel<<<(E + 255) / 256, 256>>>(ei, E);

    // GAT1 + LN + res + ELU  -> g_h
    gat1_kernel<<<(n + 7) / 8, 256>>>(att1, bias1, ln1g, ln1b, n);

    // layer-2 fused linear transforms: [xl2 | xr2 | res2 | skip] -> g_f2
    gemm_tf32<64><<<gb, 256, smemg>>>(p_h, n, p_w2, p_b2, p_f2, p_f2, p_f2, 6,
                                      ei, E, 0);

    // GAT2 + LN + res + ELU + skip + output projection -> d_out
    gat2_kernel<<<(n + 15) / 16, 256>>>(bias2, ln2g, ln2b, att2, oW, ob, out, n);
}